// round 9
// baseline (speedup 1.0000x reference)
#include <cuda_runtime.h>
#include <math.h>

typedef unsigned long long ull;

namespace {
constexpr int kB = 2, kC = 128, kHd = 64, kWd = 96, kHu = 128, kWu = 192;
constexpr int kN = kB * kHu * kWu;
constexpr int kHWd = kHd * kWd, kHWu = kHu * kWu;
}

// Precombined final-head weights: fin=[xf,cf,xf-cf] => fin@W = xf@(W0+W2) + cf@(W1-W2)
__device__ float g_WA[128 * 384];
__device__ float g_WB[128 * 384];

__global__ void prep_kernel(const float* __restrict__ o1w) {
    int i = blockIdx.x * blockDim.x + threadIdx.x;
    if (i < 128 * 384) {
        int in = i / 384, o = i - in * 384;
        float w2 = o1w[(256 + in) * 384 + o];
        g_WA[i] = o1w[in * 384 + o] + w2;
        g_WB[i] = o1w[(128 + in) * 384 + o] - w2;
    }
}

// ---- packed f32x2 helpers (SASS FFMA2 path, PTX-only) ----
__device__ __forceinline__ ull pk2(float a, float b) {
    ull r; asm("mov.b64 %0,{%1,%2};" : "=l"(r) : "f"(a), "f"(b)); return r;
}
__device__ __forceinline__ ull dup2(float a) { return pk2(a, a); }
__device__ __forceinline__ void up2(ull v, float& a, float& b) {
    asm("mov.b64 {%0,%1},%2;" : "=f"(a), "=f"(b) : "l"(v));
}
__device__ __forceinline__ ull fma2(ull a, ull b, ull c) {
    ull d; asm("fma.rn.f32x2 %0,%1,%2,%3;" : "=l"(d) : "l"(a), "l"(b), "l"(c)); return d;
}
__device__ __forceinline__ ull add2(ull a, ull b) {
    ull d; asm("add.rn.f32x2 %0,%1,%2;" : "=l"(d) : "l"(a), "l"(b)); return d;
}
__device__ __forceinline__ ull mul2(ull a, ull b) {
    ull d; asm("mul.rn.f32x2 %0,%1,%2;" : "=l"(d) : "l"(a), "l"(b)); return d;
}

// paired smem (4B per (ch,pixel), pixel-pair packed) with XOR swizzle
__device__ __forceinline__ int swzi(int f2) { return f2 ^ ((f2 >> 4) & 15); }
__device__ __forceinline__ ull ldp(const float* b, int f2) {
    return *reinterpret_cast<const ull*>(b + 2 * swzi(f2));
}
__device__ __forceinline__ void stp(float* b, int f2, ull v) {
    *reinterpret_cast<ull*>(b + 2 * swzi(f2)) = v;
}

// dup'd smem (8B per (ch,pixel), scalar stored twice). slot s = ch*4+px.
__device__ __forceinline__ ull ldd(const float* b, int s) {
    int sw = s ^ ((s >> 4) & 15);
    return *reinterpret_cast<const ull*>(b + 2 * sw);
}
__device__ __forceinline__ void sdd(float* b, int s, float v) {
    int sw = s ^ ((s >> 4) & 15);
    b[2 * sw] = v; b[2 * sw + 1] = v;
}

__device__ __forceinline__ ull wsum2(ull v) {
#pragma unroll
    for (int o = 16; o; o >>= 1) v = add2(v, __shfl_xor_sync(0xffffffffu, v, o));
    return v;
}

// pixel-paired LayerNorm (for ctx rows): v[i] packs channel (o4+i) of two pixels
__device__ __forceinline__ void ln2(const ull v[4], float eps, ull o[4]) {
    ull s = add2(add2(v[0], v[1]), add2(v[2], v[3]));
    ull q = fma2(v[0], v[0], fma2(v[1], v[1], fma2(v[2], v[2], mul2(v[3], v[3]))));
    s = wsum2(s); q = wsum2(q);
    float s0, s1, q0, q1; up2(s, s0, s1); up2(q, q0, q1);
    float m0 = s0 * (1.0f / 128.0f), m1 = s1 * (1.0f / 128.0f);
    float r0 = rsqrtf(fmaxf(q0 * (1.0f / 128.0f) - m0 * m0, 0.0f) + eps);
    float r1 = rsqrtf(fmaxf(q1 * (1.0f / 128.0f) - m1 * m1, 0.0f) + eps);
    ull nm = pk2(-m0, -m1), rr = pk2(r0, r1);
#pragma unroll
    for (int i = 0; i < 4; ++i) o[i] = mul2(add2(v[i], nm), rr);
}

// channel-paired per-pixel LayerNorm: v[px][cp] packs channels (o4+2cp, o4+2cp+1)
__device__ __forceinline__ void lnP(const ull v[4][2], float eps, ull o[4][2]) {
#pragma unroll
    for (int px = 0; px < 4; ++px) {
        ull s2 = add2(v[px][0], v[px][1]);
        ull q2 = fma2(v[px][0], v[px][0], mul2(v[px][1], v[px][1]));
        float sa, sb, qa, qb; up2(s2, sa, sb); up2(q2, qa, qb);
        ull t = wsum2(pk2(sa + sb, qa + qb));   // (sum, sqsum) reduced together
        float S, Q; up2(t, S, Q);
        float m = S * (1.0f / 128.0f);
        float r = rsqrtf(fmaxf(Q * (1.0f / 128.0f) - m * m, 0.0f) + eps);
        ull nm = dup2(-m), rr = dup2(r);
        o[px][0] = mul2(add2(v[px][0], nm), rr);
        o[px][1] = mul2(add2(v[px][1], nm), rr);
    }
}

__device__ __forceinline__ float gelu_t(float x) {
    float u = 0.7978845608028654f * (x + 0.044715f * x * x * x);
    return 0.5f * x * (1.0f + tanhf(u));
}
__device__ __forceinline__ float gelu_e(float x) { return 0.5f * x * (1.0f + erff(x * 0.7071067811865475f)); }
__device__ __forceinline__ ull gelu_e2(ull v) { float a, b; up2(v, a, b); return pk2(gelu_e(a), gelu_e(b)); }

__device__ __forceinline__ float4 ldg4(const float* p) {
    return __ldg(reinterpret_cast<const float4*>(p));
}
__device__ __forceinline__ ulonglong2 ldg2(const float* p) {
    return __ldg(reinterpret_cast<const ulonglong2*>(p));
}

// MOV-dup GEMV (pixel-paired acts in smem, weights duplicated): used for multi-row k/v/WB, fc2
template <int NIN, int ROWS, int NG, int STRIDE>
__device__ __forceinline__ void mv2(const float* __restrict__ W, const float* __restrict__ act,
                                    int actStride, int o4, ull* acc) {
#pragma unroll 2
    for (int in = 0; in < NIN; ++in) {
        ull wd[NG][4];
#pragma unroll
        for (int r = 0; r < NG; ++r) {
            float4 wv = ldg4(W + in * STRIDE + r * 128 + o4);
            wd[r][0] = dup2(wv.x); wd[r][1] = dup2(wv.y);
            wd[r][2] = dup2(wv.z); wd[r][3] = dup2(wv.w);
        }
#pragma unroll
        for (int row = 0; row < ROWS; ++row) {
            ull a0 = ldp(act + row * actStride, in * 2 + 0);
            ull a1 = ldp(act + row * actStride, in * 2 + 1);
            ull* ar = acc + row * (2 * NG * 4);
#pragma unroll
            for (int r = 0; r < NG; ++r)
#pragma unroll
                for (int i = 0; i < 4; ++i) {
                    ar[r * 4 + i]          = fma2(a0, wd[r][i], ar[r * 4 + i]);
                    ar[NG * 4 + r * 4 + i] = fma2(a1, wd[r][i], ar[NG * 4 + r * 4 + i]);
                }
        }
    }
}

// pair-scheme GEMV: weights as natural channel-pairs (0 MOVs), acts dup'd in smem.
// acc[(px*NG+g)*2+cp] += act[px][in] * W[in][g*128+o4+2cp+{0,1}]
template <int NIN, int NG, int STRIDE>
__device__ __forceinline__ void mvP(const float* __restrict__ W, const float* __restrict__ actd,
                                    int o4, ull* acc) {
#pragma unroll 4
    for (int in = 0; in < NIN; ++in) {
        ulonglong2 wp[NG];
#pragma unroll
        for (int g = 0; g < NG; ++g)
            wp[g] = ldg2(W + in * STRIDE + g * 128 + o4);
#pragma unroll
        for (int px = 0; px < 4; ++px) {
            ull a = ldd(actd, in * 4 + px);
#pragma unroll
            for (int g = 0; g < NG; ++g) {
                acc[(px * NG + g) * 2 + 0] = fma2(a, wp[g].x, acc[(px * NG + g) * 2 + 0]);
                acc[(px * NG + g) * 2 + 1] = fma2(a, wp[g].y, acc[(px * NG + g) * 2 + 1]);
            }
        }
    }
}

// store channel-paired [4][2] vector dup'd into sxd
__device__ __forceinline__ void storeP_dup(float* sxd, int o4, const ull t[4][2]) {
#pragma unroll
    for (int px = 0; px < 4; ++px)
#pragma unroll
        for (int cp = 0; cp < 2; ++cp) {
            float a, b; up2(t[px][cp], a, b);
            sdd(sxd, (o4 + 2 * cp) * 4 + px, a);
            sdd(sxd, (o4 + 2 * cp + 1) * 4 + px, b);
        }
}

__global__ __launch_bounds__(64, 8)
void upsample_tf_kernel(
    const float* __restrict__ feat, const float* __restrict__ featup,
    const float* __restrict__ ctx_ln_b,
    const float* __restrict__ q_w, const float* __restrict__ q_b,
    const float* __restrict__ k_w, const float* __restrict__ k_b,
    const float* __restrict__ v_w, const float* __restrict__ v_b,
    const float* __restrict__ o_w, const float* __restrict__ o_b,
    const float* __restrict__ fc1_w, const float* __restrict__ fc1_b,
    const float* __restrict__ fc2_w, const float* __restrict__ fc2_b,
    const float* __restrict__ out1_b,
    const float* __restrict__ out2_w, const float* __restrict__ out2_b,
    const float* __restrict__ ctx_ln_g,
    float* __restrict__ out)
{
    __shared__ __align__(16) float s_xd[2][1024];     // dup'd: xn/ov/hn/xf
    __shared__ __align__(16) float s_c[2][4][512];    // paired: cn / fc1 hidden / cf
    __shared__ __align__(16) float s_a[2][4][16];     // final logits staging

    const int w = threadIdx.x >> 5, ln = threadIdx.x & 31, o4 = ln * 4;
    const int g = blockIdx.x * 2 + w;
    const int n0 = g * 4;
    if (n0 >= kN) return;
    const int b = n0 / kHWu;
    const int rr = n0 - b * kHWu;
    const int hu = rr / kWu, wu0 = rr - hu * kWu;

    float* sxd = s_xd[w];
    float* sc = &s_c[w][0][0];
    float (*sa)[16] = s_a[w];

    const int rh0 = min(hu >> 1, kHd - 1), rh1 = min((hu >> 1) + 1, kHd - 1);
    const int hd = ln >> 3;
    const float slope = exp2f(-(float)(hd + 1) * 1.1462406251802891f); // log2(24)/4

    // ---- x load, transposed to channel-paired per pixel
    ull x2[4][2];
    {
        const float* fu = featup + ((size_t)b * kC) * kHWu + (size_t)hu * kWu + wu0;
        float4 p0 = ldg4(fu + (size_t)(o4 + 0) * kHWu);
        float4 p1 = ldg4(fu + (size_t)(o4 + 1) * kHWu);
        float4 p2 = ldg4(fu + (size_t)(o4 + 2) * kHWu);
        float4 p3 = ldg4(fu + (size_t)(o4 + 3) * kHWu);
        x2[0][0] = pk2(p0.x, p1.x); x2[0][1] = pk2(p2.x, p3.x);
        x2[1][0] = pk2(p0.y, p1.y); x2[1][1] = pk2(p2.y, p3.y);
        x2[2][0] = pk2(p0.z, p1.z); x2[2][1] = pk2(p2.z, p3.z);
        x2[3][0] = pk2(p0.w, p1.w); x2[3][1] = pk2(p2.w, p3.w);
    }

    auto loadctx = [&](int j, ull cv[2][4]) {
        const int ky = j >> 1, kx = j & 1;
        const int rhv = ky ? rh1 : rh0;
        const float* fm = feat + ((size_t)b * kC) * kHWd + rhv * kWd;
#pragma unroll
        for (int i = 0; i < 4; ++i) {
            const float* cp = fm + (size_t)(o4 + i) * kHWd;
            float v0 = __ldg(cp + min(((wu0 + 0) >> 1) + kx, kWd - 1));
            float v1 = __ldg(cp + min(((wu0 + 1) >> 1) + kx, kWd - 1));
            float v2 = __ldg(cp + min(((wu0 + 2) >> 1) + kx, kWd - 1));
            float v3 = __ldg(cp + min(((wu0 + 3) >> 1) + kx, kWd - 1));
            cv[0][i] = pk2(v0, v1);
            cv[1][i] = pk2(v2, v3);
        }
    };

#pragma unroll 1
    for (int l = 0; l < 2; ++l) {
        const float* qW  = q_w  + l * 16384;
        const float* kW  = k_w  + l * 16384;
        const float* vW  = v_w  + l * 16384;
        const float* oW  = o_w  + l * 16384;
        const float* f1W = fc1_w + l * 65536;
        const float* f2W = fc2_w + l * 65536;

        // xn = LN(x) -> sxd (dup'd)
        ull t[4][2];
        lnP(x2, 1e-6f, t);
        __syncwarp();   // previous readers of sxd done
        storeP_dup(sxd, o4, t);

        // cn = LN(ctx,1e-5)*g + b -> sc (paired)
        {
            float4 gg = ldg4(ctx_ln_g + l * 128 + o4);
            float4 bb = ldg4(ctx_ln_b + l * 128 + o4);
            ull gd[4] = {dup2(gg.x), dup2(gg.y), dup2(gg.z), dup2(gg.w)};
            ull bd[4] = {dup2(bb.x), dup2(bb.y), dup2(bb.z), dup2(bb.w)};
#pragma unroll 1
            for (int j = 0; j < 4; ++j) {
                ull cv[2][4], cn[2][4];
                loadctx(j, cv);
                ln2(cv[0], 1e-5f, cn[0]);
                ln2(cv[1], 1e-5f, cn[1]);
#pragma unroll
                for (int pr = 0; pr < 2; ++pr)
#pragma unroll
                    for (int i = 0; i < 4; ++i)
                        stp(sc + j * 512, (o4 + i) * 2 + pr, fma2(cn[pr][i], gd[i], bd[i]));
            }
        }
        __syncwarp();

        // q = xn @ q_w + q_b   (pair scheme, channel-paired out)
        ull qa8[8];
        {
            ulonglong2 bp = ldg2(q_b + l * 128 + o4);
#pragma unroll
            for (int px = 0; px < 4; ++px) { qa8[px * 2] = bp.x; qa8[px * 2 + 1] = bp.y; }
        }
        mvP<128, 1, 128>(qW, sxd, o4, qa8);
        // repack q to pixel-paired for score dot
        ull qp[2][4];
        {
            float qs[4][4];
#pragma unroll
            for (int px = 0; px < 4; ++px)
#pragma unroll
                for (int cp = 0; cp < 2; ++cp) up2(qa8[px * 2 + cp], qs[px][2 * cp], qs[px][2 * cp + 1]);
#pragma unroll
            for (int pr = 0; pr < 2; ++pr)
#pragma unroll
                for (int i = 0; i < 4; ++i) qp[pr][i] = pk2(qs[2 * pr][i], qs[2 * pr + 1][i]);
        }

        // k: all 4 ctx rows in one pass, folded into scores
        ull sc2[4][2];
        {
            ull ka[32];
            float4 kb = ldg4(k_b + l * 128 + o4);
            ull kb2[4] = {dup2(kb.x), dup2(kb.y), dup2(kb.z), dup2(kb.w)};
#pragma unroll
            for (int j = 0; j < 4; ++j)
#pragma unroll
                for (int pr = 0; pr < 2; ++pr)
#pragma unroll
                    for (int i = 0; i < 4; ++i) ka[j * 8 + pr * 4 + i] = kb2[i];
            mv2<128, 4, 1, 128>(kW, sc, 512, o4, ka);
#pragma unroll
            for (int j = 0; j < 4; ++j)
#pragma unroll
                for (int pr = 0; pr < 2; ++pr) {
                    ull p = mul2(qp[pr][0], ka[j * 8 + pr * 4 + 0]);
                    p = fma2(qp[pr][1], ka[j * 8 + pr * 4 + 1], p);
                    p = fma2(qp[pr][2], ka[j * 8 + pr * 4 + 2], p);
                    p = fma2(qp[pr][3], ka[j * 8 + pr * 4 + 3], p);
                    p = add2(p, __shfl_xor_sync(0xffffffffu, p, 1));
                    p = add2(p, __shfl_xor_sync(0xffffffffu, p, 2));
                    p = add2(p, __shfl_xor_sync(0xffffffffu, p, 4));
                    sc2[j][pr] = p;
                }
        }

        // softmax with ALiBi, per pixel (redundant per lane)
        ull a2[4][2];
        {
#pragma unroll
            for (int pr = 0; pr < 2; ++pr) {
                float sj[2][4];
#pragma unroll
                for (int j = 0; j < 4; ++j) {
                    float pa, pb; up2(sc2[j][pr], pa, pb);
                    const int ky = j >> 1, kx = j & 1;
                    const int rhv = ky ? rh1 : rh0;
#pragma unroll
                    for (int tt = 0; tt < 2; ++tt) {
                        int wup = wu0 + pr * 2 + tt;
                        int rwv = min((wup >> 1) + kx, kWd - 1);
                        float cd = -(float)(abs(hu - 2 * rhv) + abs(wup - 2 * rwv));
                        sj[tt][j] = (tt ? pb : pa) * 0.17677669529663687f + slope * cd;
                    }
                }
                float av[2][4];
#pragma unroll
                for (int tt = 0; tt < 2; ++tt) {
                    float mx = fmaxf(fmaxf(sj[tt][0], sj[tt][1]), fmaxf(sj[tt][2], sj[tt][3]));
                    float e0 = expf(sj[tt][0] - mx), e1 = expf(sj[tt][1] - mx);
                    float e2 = expf(sj[tt][2] - mx), e3 = expf(sj[tt][3] - mx);
                    float inv = 1.0f / (e0 + e1 + e2 + e3);
                    av[tt][0] = e0 * inv; av[tt][1] = e1 * inv;
                    av[tt][2] = e2 * inv; av[tt][3] = e3 * inv;
                }
#pragma unroll
                for (int j = 0; j < 4; ++j) a2[j][pr] = pk2(av[0][j], av[1][j]);
            }
        }

        // v in 2-row passes folded into ov (pixel-paired)
        ull ov[2][4];
        {
            float4 vb = ldg4(v_b + l * 128 + o4);
            ull vb2[4] = {dup2(vb.x), dup2(vb.y), dup2(vb.z), dup2(vb.w)};
#pragma unroll
            for (int pr = 0; pr < 2; ++pr)
#pragma unroll
                for (int i = 0; i < 4; ++i) ov[pr][i] = pk2(0.f, 0.f);
#pragma unroll 1
            for (int jp = 0; jp < 2; ++jp) {
                ull va[16];
#pragma unroll
                for (int row = 0; row < 2; ++row)
#pragma unroll
                    for (int pr = 0; pr < 2; ++pr)
#pragma unroll
                        for (int i = 0; i < 4; ++i) va[row * 8 + pr * 4 + i] = vb2[i];
                mv2<128, 2, 1, 128>(vW, sc + jp * 1024, 512, o4, va);
#pragma unroll
                for (int row = 0; row < 2; ++row)
#pragma unroll
                    for (int pr = 0; pr < 2; ++pr)
#pragma unroll
                        for (int i = 0; i < 4; ++i)
                            ov[pr][i] = fma2(a2[jp * 2 + row][pr], va[row * 8 + pr * 4 + i], ov[pr][i]);
            }
        }
        __syncwarp();   // q-pass reads of sxd done
        // store ov dup'd
#pragma unroll
        for (int pr = 0; pr < 2; ++pr)
#pragma unroll
            for (int i = 0; i < 4; ++i) {
                float a, bv; up2(ov[pr][i], a, bv);
                sdd(sxd, (o4 + i) * 4 + 2 * pr + 0, a);
                sdd(sxd, (o4 + i) * 4 + 2 * pr + 1, bv);
            }
        __syncwarp();

        // x += o @ o_w + o_b  (pair scheme, adds directly to channel-paired x2)
        {
            ull oa8[8];
            ulonglong2 bp = ldg2(o_b + l * 128 + o4);
#pragma unroll
            for (int px = 0; px < 4; ++px) { oa8[px * 2] = bp.x; oa8[px * 2 + 1] = bp.y; }
            mvP<128, 1, 128>(oW, sxd, o4, oa8);
#pragma unroll
            for (int px = 0; px < 4; ++px) {
                x2[px][0] = add2(x2[px][0], oa8[px * 2 + 0]);
                x2[px][1] = add2(x2[px][1], oa8[px * 2 + 1]);
            }
        }

        // MLP
        lnP(x2, 1e-6f, t);
        __syncwarp();   // o-proj reads of sxd done
        storeP_dup(sxd, o4, t);
        __syncwarp();

        // fc1: NG=4 pair scheme
        {
            ull f1[32];   // [(px*4+g)*2+cp]
#pragma unroll
            for (int gg = 0; gg < 4; ++gg) {
                ulonglong2 bp = ldg2(fc1_b + l * 512 + gg * 128 + o4);
#pragma unroll
                for (int px = 0; px < 4; ++px) {
                    f1[(px * 4 + gg) * 2 + 0] = bp.x;
                    f1[(px * 4 + gg) * 2 + 1] = bp.y;
                }
            }
            mvP<128, 4, 512>(f1W, sxd, o4, f1);
            __syncwarp();   // v-pass reads of sc done
#pragma unroll
            for (int gg = 0; gg < 4; ++gg)
#pragma unroll
                for (int cp = 0; cp < 2; ++cp) {
                    float a0, b0, a1, b1, a2_, b2, a3, b3;
                    up2(f1[(0 * 4 + gg) * 2 + cp], a0, b0);
                    up2(f1[(1 * 4 + gg) * 2 + cp], a1, b1);
                    up2(f1[(2 * 4 + gg) * 2 + cp], a2_, b2);
                    up2(f1[(3 * 4 + gg) * 2 + cp], a3, b3);
                    int c0 = gg * 128 + o4 + 2 * cp, c1 = c0 + 1;
                    stp(sc, c0 * 2 + 0, pk2(gelu_t(a0), gelu_t(a1)));
                    stp(sc, c0 * 2 + 1, pk2(gelu_t(a2_), gelu_t(a3)));
                    stp(sc, c1 * 2 + 0, pk2(gelu_t(b0), gelu_t(b1)));
                    stp(sc, c1 * 2 + 1, pk2(gelu_t(b2), gelu_t(b3)));
                }
            __syncwarp();
        }

        // fc2 on paired hidden
        {
            ull fa8[8];
            float4 fb = ldg4(fc2_b + l * 128 + o4);
            fa8[0] = fa8[4] = dup2(fb.x); fa8[1] = fa8[5] = dup2(fb.y);
            fa8[2] = fa8[6] = dup2(fb.z); fa8[3] = fa8[7] = dup2(fb.w);
            mv2<512, 1, 1, 128>(f2W, sc, 0, o4, fa8);
            // transpose pixel-paired -> channel-paired and add
            float tpx[4][4];
#pragma unroll
            for (int pr = 0; pr < 2; ++pr)
#pragma unroll
                for (int i = 0; i < 4; ++i) up2(fa8[pr * 4 + i], tpx[2 * pr][i], tpx[2 * pr + 1][i]);
#pragma unroll
            for (int px = 0; px < 4; ++px) {
                x2[px][0] = add2(x2[px][0], pk2(tpx[px][0], tpx[px][1]));
                x2[px][1] = add2(x2[px][1], pk2(tpx[px][2], tpx[px][3]));
            }
        }
        __syncwarp();   // fc2 reads of sc done before next-layer cn overwrite
    }

    // ---- final head
    {
        ull t[4][2];
        lnP(x2, 1e-6f, t);   // xf
        __syncwarp();
        storeP_dup(sxd, o4, t);
#pragma unroll 1
        for (int j = 0; j < 4; ++j) {
            ull cv[2][4], cf[2][4];
            loadctx(j, cv);
            ln2(cv[0], 1e-6f, cf[0]);
            ln2(cv[1], 1e-6f, cf[1]);
#pragma unroll
            for (int pr = 0; pr < 2; ++pr)
#pragma unroll
                for (int i = 0; i < 4; ++i) stp(sc + j * 512, (o4 + i) * 2 + pr, cf[pr][i]);
        }
        __syncwarp();

        ull s2[4][2];
#pragma unroll
        for (int j = 0; j < 4; ++j) { s2[j][0] = pk2(0.f, 0.f); s2[j][1] = pk2(0.f, 0.f); }

#pragma unroll 1
        for (int r = 0; r < 3; ++r) {
            // tb = out1_b[r] + xf @ WA[:,r-cols]  (pair scheme)
            ull tb8[8];
            {
                ulonglong2 bp = ldg2(out1_b + r * 128 + o4);
#pragma unroll
                for (int px = 0; px < 4; ++px) { tb8[px * 2] = bp.x; tb8[px * 2 + 1] = bp.y; }
            }
            mvP<128, 1, 384>(g_WA + r * 128, sxd, o4, tb8);
            // transpose to pixel-paired
            ull tpp[2][4];
            {
                float ts[4][4];
#pragma unroll
                for (int px = 0; px < 4; ++px)
#pragma unroll
                    for (int cp = 0; cp < 2; ++cp) up2(tb8[px * 2 + cp], ts[px][2 * cp], ts[px][2 * cp + 1]);
#pragma unroll
                for (int pr = 0; pr < 2; ++pr)
#pragma unroll
                    for (int i = 0; i < 4; ++i) tpp[pr][i] = pk2(ts[2 * pr][i], ts[2 * pr + 1][i]);
            }

            float4 w2v = ldg4(out2_w + r * 128 + o4);
            ull wd[4] = {dup2(w2v.x), dup2(w2v.y), dup2(w2v.z), dup2(w2v.w)};

#pragma unroll 1
            for (int jp = 0; jp < 2; ++jp) {
                ull us[16];
#pragma unroll
                for (int tt = 0; tt < 16; ++tt) us[tt] = pk2(0.f, 0.f);
                mv2<128, 2, 1, 384>(g_WB + r * 128, sc + jp * 1024, 512, o4, us);
#pragma unroll
                for (int row = 0; row < 2; ++row)
#pragma unroll
                    for (int pr = 0; pr < 2; ++pr)
#pragma unroll
                        for (int i = 0; i < 4; ++i)
                            s2[jp * 2 + row][pr] = fma2(gelu_e2(add2(tpp[pr][i], us[row * 8 + pr * 4 + i])),
                                                        wd[i], s2[jp * 2 + row][pr]);
            }
        }

        const float o2b = __ldg(out2_b);
#pragma unroll
        for (int j = 0; j < 4; ++j)
#pragma unroll
            for (int pr = 0; pr < 2; ++pr) {
                ull tt = wsum2(s2[j][pr]);
                float a, bv; up2(tt, a, bv);
                if (ln == 0) {
                    sa[pr * 2][j] = a + o2b;
                    sa[pr * 2 + 1][j] = bv + o2b;
                }
            }
        __syncwarp();

        if (ln < 16) {
            int p = ln >> 2, j = ln & 3;
            float l0 = sa[p][0], l1 = sa[p][1], l2 = sa[p][2], l3 = sa[p][3];
            float mx = fmaxf(fmaxf(l0, l1), fmaxf(l2, l3));
            float den = expf(l0 - mx) + expf(l1 - mx) + expf(l2 - mx) + expf(l3 - mx);
            float e = expf(sa[p][j] - mx);
            out[(((size_t)b * 4 + j) * kHu + hu) * kWu + wu0 + p] = e / den;
        }
    }
}

extern "C" void kernel_launch(void* const* d_in, const int* in_sizes, int n_in,
                              void* d_out, int out_size) {
    const float* feat     = (const float*)d_in[0];
    const float* featup   = (const float*)d_in[1];
    const float* ctx_ln_b = (const float*)d_in[2];
    const float* q_w      = (const float*)d_in[3];
    const float* q_b      = (const float*)d_in[4];
    const float* k_w      = (const float*)d_in[5];
    const float* k_b      = (const float*)d_in[6];
    const float* v_w      = (const float*)d_in[7];
    const float* v_b      = (const float*)d_in[8];
    const float* o_w      = (const float*)d_in[9];
    const float* o_b      = (const float*)d_in[10];
    const float* fc1_w    = (const float*)d_in[11];
    const float* fc1_b    = (const float*)d_in[12];
    const float* fc2_w    = (const float*)d_in[13];
    const float* fc2_b    = (const float*)d_in[14];
    const float* out1_w   = (const float*)d_in[15];
    const float* out1_b   = (const float*)d_in[16];
    const float* out2_w   = (const float*)d_in[17];
    const float* out2_b   = (const float*)d_in[18];
    const float* ctx_ln_g = (const float*)d_in[19];

    prep_kernel<<<(128 * 384 + 255) / 256, 256>>>(out1_w);
    upsample_tf_kernel<<<kN / 8, 64>>>(
        feat, featup, ctx_ln_b, q_w, q_b, k_w, k_b, v_w, v_b, o_w, o_b,
        fc1_w, fc1_b, fc2_w, fc2_b, out1_b, out2_w, out2_b, ctx_ln_g,
        (float*)d_out);
}